// round 2
// baseline (speedup 1.0000x reference)
#include <cuda_runtime.h>
#include <cuda_bf16.h>

// Problem constants
#define BATCH 4
#define SEQ   2048
#define DMODEL 1280
#define NHEAD 16
#define HDIM  80
#define MTOT  (BATCH*SEQ)          // 8192
#define NQKV  (3*NHEAD*HDIM)       // 3840

// Scratch (allocation-free: __device__ globals)
__device__ float g_q[BATCH*NHEAD*SEQ*HDIM];       // [B,H,S,HD]
__device__ float g_k[BATCH*NHEAD*SEQ*HDIM];
__device__ float g_v[BATCH*NHEAD*SEQ*HDIM];
__device__ float g_attn[MTOT*DMODEL];             // [B,S,H*HD]
__device__ float g_scale[HDIM];

// ---------------------------------------------------------------------------
// Kernel 0: per-dim query scale = softplus(scaling) * log2(e) / sqrt(HD)
// ---------------------------------------------------------------------------
__global__ void scale_kernel(const float* __restrict__ scaling) {
    int i = threadIdx.x;
    if (i < HDIM) {
        float x = scaling[i];
        float sp = (x > 20.f) ? x : log1pf(expf(x));
        g_scale[i] = sp * 1.442695041f * rsqrtf((float)HDIM);
    }
}

// ---------------------------------------------------------------------------
// SGEMM: C[m,n] = sum_k A[m,k]*W[n,k] (+bias)    A:[M,K] W:[N,K] row-major
// 128x128 tile, BK=8, 256 threads, 8x8 register micro-tile.
// MODE 0: QKV epilogue (bias, q-scale, scatter to g_q/g_k/g_v)
// MODE 1: plain epilogue (bias, write C row-major [M,N])
// ---------------------------------------------------------------------------
#define BM 128
#define BN 128
#define BKD 8

template<int MODE>
__global__ __launch_bounds__(256)
void sgemm_kernel(const float* __restrict__ A, const float* __restrict__ W,
                  const float* __restrict__ bias, float* __restrict__ C,
                  int M, int N, int K)
{
    __shared__ float As[BKD][BM + 4];
    __shared__ float Bs[BKD][BN + 4];

    const int tid = threadIdx.x;
    const int m0 = blockIdx.y * BM;
    const int n0 = blockIdx.x * BN;

    const int lr = tid >> 1;          // 0..127
    const int lc = (tid & 1) * 4;     // 0 or 4
    const float* Aptr = A + (long)(m0 + lr) * K + lc;
    const float* Wptr = W + (long)(n0 + lr) * K + lc;

    const int row = (tid >> 4) * 8;   // 0..120
    const int col = (tid & 15) * 8;   // 0..120

    float acc[8][8];
#pragma unroll
    for (int i = 0; i < 8; ++i)
#pragma unroll
        for (int j = 0; j < 8; ++j) acc[i][j] = 0.f;

    for (int k0 = 0; k0 < K; k0 += BKD) {
        float4 av = *(const float4*)(Aptr + k0);
        float4 bv = *(const float4*)(Wptr + k0);
        As[lc + 0][lr] = av.x; As[lc + 1][lr] = av.y;
        As[lc + 2][lr] = av.z; As[lc + 3][lr] = av.w;
        Bs[lc + 0][lr] = bv.x; Bs[lc + 1][lr] = bv.y;
        Bs[lc + 2][lr] = bv.z; Bs[lc + 3][lr] = bv.w;
        __syncthreads();
#pragma unroll
        for (int k = 0; k < BKD; ++k) {
            float a[8], b[8];
#pragma unroll
            for (int i = 0; i < 8; ++i) a[i] = As[k][row + i];
#pragma unroll
            for (int j = 0; j < 8; ++j) b[j] = Bs[k][col + j];
#pragma unroll
            for (int i = 0; i < 8; ++i)
#pragma unroll
                for (int j = 0; j < 8; ++j)
                    acc[i][j] += a[i] * b[j];
        }
        __syncthreads();
    }

    if (MODE == 1) {
#pragma unroll
        for (int i = 0; i < 8; ++i) {
            int gm = m0 + row + i;
#pragma unroll
            for (int j = 0; j < 8; ++j) {
                int gn = n0 + col + j;
                C[(long)gm * N + gn] = acc[i][j] + bias[gn];
            }
        }
    } else {
#pragma unroll
        for (int i = 0; i < 8; ++i) {
            int gm = m0 + row + i;
            int b  = gm >> 11;          // /SEQ
            int s  = gm & (SEQ - 1);
#pragma unroll
            for (int j = 0; j < 8; ++j) {
                int gn = n0 + col + j;
                float v = acc[i][j] + bias[gn];
                int which = gn / (NHEAD * HDIM);
                int r     = gn % (NHEAD * HDIM);
                int h = r / HDIM;
                int d = r % HDIM;
                if (which == 0) v *= g_scale[d];
                int idx = (((b * NHEAD + h) * SEQ + s) * HDIM) + d;
                float* dst = (which == 0) ? g_q : (which == 1) ? g_k : g_v;
                dst[idx] = v;
            }
        }
    }
}

// ---------------------------------------------------------------------------
// Flash attention (causal), fp32 SIMT.
// Grid: (SEQ/128, B*H). Block: 256 threads. 2 threads per query row,
// each owns 40 of 80 head dims; partner-combine dot products via shfl.xor.
// K/V staged in smem 32 rows at a time; online softmax.
// ---------------------------------------------------------------------------
__global__ __launch_bounds__(256)
void flash_kernel(const float* __restrict__ gq, const float* __restrict__ gk,
                  const float* __restrict__ gv, float* __restrict__ gout)
{
    __shared__ float Ks[32 * HDIM];
    __shared__ float Vs[32 * HDIM];

    const int tid  = threadIdx.x;
    const int bh   = blockIdx.y;
    const int qb   = blockIdx.x;
    const int r    = tid >> 1;
    const int doff = (tid & 1) * 40;
    const int qi   = qb * 128 + r;

    const float* qptr = gq + (((long)bh * SEQ + qi) * HDIM) + doff;
    float q[40], o[40];
#pragma unroll
    for (int i = 0; i < 40; ++i) { q[i] = qptr[i]; o[i] = 0.f; }

    float mrow = -1e30f, lrow = 0.f;

    const float* kb = gk + (long)bh * SEQ * HDIM;
    const float* vb = gv + (long)bh * SEQ * HDIM;
    const int ntiles = qb * 4 + 4;   // causal: keys up to qb*128+127

    for (int t = 0; t < ntiles; ++t) {
        const int kt0 = t * 32;
        // cooperative load of K,V tiles (contiguous 2560 floats each)
#pragma unroll
        for (int u = 0; u < 10; ++u) {
            int idx = tid + u * 256;
            Ks[idx] = kb[kt0 * HDIM + idx];
            Vs[idx] = vb[kt0 * HDIM + idx];
        }
        __syncthreads();

        if (kt0 <= qi) {
            float s[32];
#pragma unroll
            for (int j = 0; j < 32; ++j) {
                const float4* kr = (const float4*)&Ks[j * HDIM + doff];
                float acc = 0.f;
#pragma unroll
                for (int d4 = 0; d4 < 10; ++d4) {
                    float4 kv = kr[d4];
                    acc += q[d4*4+0]*kv.x + q[d4*4+1]*kv.y
                         + q[d4*4+2]*kv.z + q[d4*4+3]*kv.w;
                }
                s[j] = acc;
            }
#pragma unroll
            for (int j = 0; j < 32; ++j)
                s[j] += __shfl_xor_sync(0xffffffffu, s[j], 1);
#pragma unroll
            for (int j = 0; j < 32; ++j)
                if (kt0 + j > qi) s[j] = -1e30f;

            float newm = mrow;
#pragma unroll
            for (int j = 0; j < 32; ++j) newm = fmaxf(newm, s[j]);
            float alpha = expf(mrow - newm);
            lrow *= alpha;
#pragma unroll
            for (int i = 0; i < 40; ++i) o[i] *= alpha;
#pragma unroll
            for (int j = 0; j < 32; ++j) {
                float pj = expf(s[j] - newm);
                lrow += pj;
                const float4* vr = (const float4*)&Vs[j * HDIM + doff];
#pragma unroll
                for (int d4 = 0; d4 < 10; ++d4) {
                    float4 vv = vr[d4];
                    o[d4*4+0] += pj * vv.x; o[d4*4+1] += pj * vv.y;
                    o[d4*4+2] += pj * vv.z; o[d4*4+3] += pj * vv.w;
                }
            }
            mrow = newm;
        }
        __syncthreads();
    }

    const float inv = 1.f / lrow;
    const int b = bh >> 4, h = bh & 15;
    float* op = gout + ((((long)b * SEQ + qi) * NHEAD + h) * HDIM) + doff;
#pragma unroll
    for (int i = 0; i < 40; ++i) op[i] = o[i] * inv;
}

// ---------------------------------------------------------------------------
// Launch
// ---------------------------------------------------------------------------
extern "C" void kernel_launch(void* const* d_in, const int* in_sizes, int n_in,
                              void* d_out, int out_size)
{
    const float* hidden  = (const float*)d_in[0];
    // d_in[1] = attention_mask: exact additive causal mask; implemented directly.
    const float* scaling = (const float*)d_in[2];
    const float* qkv_w   = (const float*)d_in[3];
    const float* qkv_b   = (const float*)d_in[4];
    const float* o_w     = (const float*)d_in[5];
    const float* o_b     = (const float*)d_in[6];
    float* out = (float*)d_out;

    float *gq, *gk, *gv, *gattn;
    cudaGetSymbolAddress((void**)&gq,    g_q);
    cudaGetSymbolAddress((void**)&gk,    g_k);
    cudaGetSymbolAddress((void**)&gv,    g_v);
    cudaGetSymbolAddress((void**)&gattn, g_attn);

    scale_kernel<<<1, 128>>>(scaling);

    dim3 gqkv(NQKV / BN, MTOT / BM);
    sgemm_kernel<0><<<gqkv, 256>>>(hidden, qkv_w, qkv_b, nullptr,
                                   MTOT, NQKV, DMODEL);

    dim3 gfl(SEQ / 128, BATCH * NHEAD);
    flash_kernel<<<gfl, 256>>>(gq, gk, gv, gattn);

    dim3 gproj(DMODEL / BN, MTOT / BM);
    sgemm_kernel<1><<<gproj, 256>>>(gattn, o_w, o_b, out,
                                    MTOT, DMODEL, DMODEL);
}

// round 6
// speedup vs baseline: 1.3382x; 1.3382x over previous
#include <cuda_runtime.h>
#include <cuda_bf16.h>
#include <cstdint>

// Problem constants
#define BATCH 4
#define SEQ   2048
#define DMODEL 1280
#define NHEAD 16
#define HDIM  80
#define MTOT  (BATCH*SEQ)          // 8192
#define NQKV  (3*NHEAD*HDIM)       // 3840
#define HH    (NHEAD*HDIM)         // 1280

// ---------------------------------------------------------------------------
// Scratch (__device__ globals; no allocation anywhere)
// ---------------------------------------------------------------------------
__device__ float         g_qkv[(size_t)MTOT*NQKV];     // [B*S, 3*H*HD] fp32
__device__ __nv_bfloat16 g_h_hi[(size_t)MTOT*DMODEL];
__device__ __nv_bfloat16 g_h_lo[(size_t)MTOT*DMODEL];
__device__ __nv_bfloat16 g_w1_hi[(size_t)NQKV*DMODEL];
__device__ __nv_bfloat16 g_w1_lo[(size_t)NQKV*DMODEL];
__device__ __nv_bfloat16 g_w2_hi[(size_t)DMODEL*HH];
__device__ __nv_bfloat16 g_w2_lo[(size_t)DMODEL*HH];
__device__ __nv_bfloat16 g_a_hi[(size_t)MTOT*HH];
__device__ __nv_bfloat16 g_a_lo[(size_t)MTOT*HH];
__device__ float         g_scale[HDIM];

// ---------------------------------------------------------------------------
// PTX helpers (all plain-sm_103 compatible: no tcgen05 / arch-specific ops)
// ---------------------------------------------------------------------------
__device__ __forceinline__ uint32_t s2u(const void* p) {
    uint32_t a;
    asm("{ .reg .u64 t; cvta.to.shared.u64 t, %1; cvt.u32.u64 %0, t; }"
        : "=r"(a) : "l"(p));
    return a;
}

__device__ __forceinline__ void cp_async16(uint32_t saddr, const void* gptr) {
    asm volatile("cp.async.cg.shared.global [%0], [%1], 16;"
                 :: "r"(saddr), "l"(gptr) : "memory");
}
__device__ __forceinline__ void cp_commit() {
    asm volatile("cp.async.commit_group;" ::: "memory");
}
template<int N>
__device__ __forceinline__ void cp_wait() {
    asm volatile("cp.async.wait_group %0;" :: "n"(N) : "memory");
}

__device__ __forceinline__ void ldm_x4(uint32_t* r, uint32_t addr) {
    asm volatile("ldmatrix.sync.aligned.m8n8.x4.shared.b16 {%0,%1,%2,%3}, [%4];"
                 : "=r"(r[0]), "=r"(r[1]), "=r"(r[2]), "=r"(r[3]) : "r"(addr));
}

__device__ __forceinline__ void mma16816(float* c, const uint32_t* a,
                                         uint32_t b0, uint32_t b1) {
    asm volatile(
        "mma.sync.aligned.m16n8k16.row.col.f32.bf16.bf16.f32 "
        "{%0,%1,%2,%3},{%4,%5,%6,%7},{%8,%9},{%0,%1,%2,%3};"
        : "+f"(c[0]), "+f"(c[1]), "+f"(c[2]), "+f"(c[3])
        : "r"(a[0]), "r"(a[1]), "r"(a[2]), "r"(a[3]), "r"(b0), "r"(b1));
}

// ---------------------------------------------------------------------------
// Kernel: per-dim query scale. Includes an EXTRA log2(e) so attention scores
// live in the log2 domain (exp2 in flash == reference e-softmax).
// ---------------------------------------------------------------------------
__global__ void scale_kernel(const float* __restrict__ scaling) {
    int i = threadIdx.x;
    if (i < HDIM) {
        float x = scaling[i];
        float sp = (x > 20.f) ? x : log1pf(expf(x));
        g_scale[i] = sp * 1.442695041f * rsqrtf((float)HDIM) * 1.442695041f;
    }
}

// ---------------------------------------------------------------------------
// Kernel: fp32 -> bf16 hi/lo split (x = hi + lo to ~16 mantissa bits)
// ---------------------------------------------------------------------------
__global__ void cvt_split(const float* __restrict__ x,
                          __nv_bfloat16* __restrict__ hi,
                          __nv_bfloat16* __restrict__ lo, int n4) {
    int i = blockIdx.x * blockDim.x + threadIdx.x;
    if (i >= n4) return;
    float4 v = ((const float4*)x)[i];
    __nv_bfloat16 h0 = __float2bfloat16(v.x);
    __nv_bfloat16 h1 = __float2bfloat16(v.y);
    __nv_bfloat16 h2 = __float2bfloat16(v.z);
    __nv_bfloat16 h3 = __float2bfloat16(v.w);
    __nv_bfloat162 hh0; hh0.x = h0; hh0.y = h1;
    __nv_bfloat162 hh1; hh1.x = h2; hh1.y = h3;
    __nv_bfloat162 ll0, ll1;
    ll0.x = __float2bfloat16(v.x - __bfloat162float(h0));
    ll0.y = __float2bfloat16(v.y - __bfloat162float(h1));
    ll1.x = __float2bfloat16(v.z - __bfloat162float(h2));
    ll1.y = __float2bfloat16(v.w - __bfloat162float(h3));
    ((__nv_bfloat162*)hi)[2*i]   = hh0;
    ((__nv_bfloat162*)hi)[2*i+1] = hh1;
    ((__nv_bfloat162*)lo)[2*i]   = ll0;
    ((__nv_bfloat162*)lo)[2*i+1] = ll1;
}

// ---------------------------------------------------------------------------
// HMMA GEMM:  C[m,n] = sum_k A[m,k]*B[n,k] + bias[n]  (MODE 0: *g_scale on q)
// bf16 hi/lo 3-pass (hh + lh + hl). CTA 128x128, BK=32, 8 warps of 64x32.
// cp.async double-buffered smem, 80B row stride (conflict-free ldmatrix).
// ---------------------------------------------------------------------------
#define GK     DMODEL        // 1280
#define KCH    (GK/32)       // 40 chunks per pass
#define NIT    (3*KCH)       // 120

template<int MODE>
__global__ __launch_bounds__(256)
void mma_gemm(const __nv_bfloat16* __restrict__ Ahi, const __nv_bfloat16* __restrict__ Alo,
              const __nv_bfloat16* __restrict__ Bhi, const __nv_bfloat16* __restrict__ Blo,
              const float* __restrict__ bias, float* __restrict__ dst, int Nld)
{
    __shared__ __align__(16) unsigned char sA[2][128 * 80];
    __shared__ __align__(16) unsigned char sB[2][128 * 80];

    const int tid  = threadIdx.x;
    const int lane = tid & 31;
    const int wid  = tid >> 5;
    const int wm   = wid >> 2;        // 0..1 -> 64 rows
    const int wn   = wid & 3;         // 0..3 -> 32 cols
    const int m0   = blockIdx.y * 128;
    const int n0   = blockIdx.x * 128;

    float acc[4][4][4];
#pragma unroll
    for (int a = 0; a < 4; ++a)
#pragma unroll
        for (int b = 0; b < 4; ++b)
#pragma unroll
            for (int c = 0; c < 4; ++c) acc[a][b][c] = 0.f;

    const int lrow = tid >> 2;        // 0..63
    const int lchk = tid & 3;         // 0..3 (16B chunks of a 64B row)

    // issue global->smem loads for chunk cc into buffer buf
    auto issue = [&](int cc, int buf) {
        const int seg = cc / KCH;
        const int k0  = (cc % KCH) * 32;
        const __nv_bfloat16* Ap = (seg == 1) ? Alo : Ahi;
        const __nv_bfloat16* Bp = (seg == 2) ? Blo : Bhi;
#pragma unroll
        for (int h = 0; h < 2; ++h) {
            int r = lrow + h * 64;
            cp_async16(s2u(&sA[buf][r * 80 + lchk * 16]),
                       Ap + (size_t)(m0 + r) * GK + k0 + lchk * 8);
            cp_async16(s2u(&sB[buf][r * 80 + lchk * 16]),
                       Bp + (size_t)(n0 + r) * GK + k0 + lchk * 8);
        }
    };

    issue(0, 0);
    cp_commit();

    for (int cc = 0; cc < NIT; ++cc) {
        const int buf = cc & 1;
        if (cc + 1 < NIT) {
            issue(cc + 1, buf ^ 1);
            cp_commit();
            cp_wait<1>();
        } else {
            cp_wait<0>();
        }
        __syncthreads();

#pragma unroll
        for (int ks = 0; ks < 2; ++ks) {
            uint32_t af[4][4];
#pragma unroll
            for (int ms = 0; ms < 4; ++ms) {
                int row  = wm * 64 + ms * 16 + (lane & 15);
                int khal = ks * 16 + (lane >> 4) * 8;
                ldm_x4(af[ms], s2u(&sA[buf][row * 80 + khal * 2]));
            }
            uint32_t bf[2][4];
#pragma unroll
            for (int nb = 0; nb < 2; ++nb) {
                int sel  = lane >> 3;
                int nrow = wn * 32 + nb * 16 + (lane & 7) + (sel >> 1) * 8;
                int khal = ks * 16 + (sel & 1) * 8;
                ldm_x4(bf[nb], s2u(&sB[buf][nrow * 80 + khal * 2]));
            }
#pragma unroll
            for (int ms = 0; ms < 4; ++ms)
#pragma unroll
                for (int ns = 0; ns < 4; ++ns) {
                    const uint32_t* bb = bf[ns >> 1];
                    if (ns & 1) mma16816(acc[ms][ns], af[ms], bb[2], bb[3]);
                    else        mma16816(acc[ms][ns], af[ms], bb[0], bb[1]);
                }
        }
        __syncthreads();
    }

    // Epilogue: bias (+ q-scale for MODE 0), fp32 stores
    const int qr = lane >> 2;
    const int qc = lane & 3;
#pragma unroll
    for (int ms = 0; ms < 4; ++ms) {
        int mrow = m0 + wm * 64 + ms * 16 + qr;
#pragma unroll
        for (int ns = 0; ns < 4; ++ns) {
            int ncol = n0 + wn * 32 + ns * 8 + qc * 2;
            float b0 = bias[ncol], b1 = bias[ncol + 1];
            float s0 = 1.f, s1 = 1.f;
            if (MODE == 0 && ncol < HH) {
                int d = ncol % HDIM;
                s0 = g_scale[d];
                s1 = g_scale[d + 1];
            }
            float2 v0, v1;
            v0.x = (acc[ms][ns][0] + b0) * s0;
            v0.y = (acc[ms][ns][1] + b1) * s1;
            v1.x = (acc[ms][ns][2] + b0) * s0;
            v1.y = (acc[ms][ns][3] + b1) * s1;
            *(float2*)&dst[(size_t)mrow * Nld + ncol]       = v0;
            *(float2*)&dst[(size_t)(mrow + 8) * Nld + ncol] = v1;
        }
    }
}

// ---------------------------------------------------------------------------
// Fast exp2 on FMA pipe (no MUFU). x <= 0 always here; clamp at -126.
// ---------------------------------------------------------------------------
__device__ __forceinline__ float exp2f_fast(float x) {
    x = fmaxf(x, -126.f);
    float t = rintf(x);
    float f = x - t;
    float p = 1.3333558e-3f;
    p = fmaf(p, f, 9.6181291e-3f);
    p = fmaf(p, f, 5.5504109e-2f);
    p = fmaf(p, f, 2.4022651e-1f);
    p = fmaf(p, f, 6.9314718e-1f);
    p = fmaf(p, f, 1.0f);
    return __int_as_float(__float_as_int(p) + (((int)t) << 23));
}

// ---------------------------------------------------------------------------
// Flash attention (causal), log2-domain softmax, fp32 SIMT.
// Reads q/k/v straight out of g_qkv [B*S, 3840]; writes output as bf16 hi/lo.
// ---------------------------------------------------------------------------
__global__ __launch_bounds__(256)
void flash_kernel(const float* __restrict__ qkv,
                  __nv_bfloat16* __restrict__ ahi,
                  __nv_bfloat16* __restrict__ alo)
{
    __shared__ float Ks[32 * HDIM];
    __shared__ float Vs[32 * HDIM];

    const int tid  = threadIdx.x;
    const int bh   = blockIdx.y;
    const int b    = bh >> 4, h = bh & 15;
    const int qb   = blockIdx.x;
    const int r    = tid >> 1;
    const int doff = (tid & 1) * 40;
    const int qi   = qb * 128 + r;

    const float* qptr = qkv + (size_t)(b * SEQ + qi) * NQKV + h * HDIM + doff;
    float q[40], o[40];
#pragma unroll
    for (int i = 0; i < 40; ++i) { q[i] = qptr[i]; o[i] = 0.f; }

    float mrow = -1e30f, lrow = 0.f;

    const float* kbase = qkv + (size_t)b * SEQ * NQKV + HH     + h * HDIM;
    const float* vbase = qkv + (size_t)b * SEQ * NQKV + 2 * HH + h * HDIM;
    const int ntiles = qb * 4 + 4;

    for (int t = 0; t < ntiles; ++t) {
        const int kt0 = t * 32;
        for (int i4 = tid; i4 < 640; i4 += 256) {
            int row = i4 / 20, c4 = i4 % 20;
            ((float4*)Ks)[row * 20 + c4] =
                *(const float4*)(kbase + (size_t)(kt0 + row) * NQKV + c4 * 4);
            ((float4*)Vs)[row * 20 + c4] =
                *(const float4*)(vbase + (size_t)(kt0 + row) * NQKV + c4 * 4);
        }
        __syncthreads();

        if (kt0 <= qi) {
            float s[32];
#pragma unroll
            for (int j = 0; j < 32; ++j) {
                const float4* kr = (const float4*)&Ks[j * HDIM + doff];
                float acc = 0.f;
#pragma unroll
                for (int d4 = 0; d4 < 10; ++d4) {
                    float4 kv = kr[d4];
                    acc += q[d4*4+0]*kv.x + q[d4*4+1]*kv.y
                         + q[d4*4+2]*kv.z + q[d4*4+3]*kv.w;
                }
                s[j] = acc;
            }
#pragma unroll
            for (int j = 0; j < 32; ++j)
                s[j] += __shfl_xor_sync(0xffffffffu, s[j], 1);
#pragma unroll
            for (int j = 0; j < 32; ++j)
                if (kt0 + j > qi) s[j] = -1e30f;

            float newm = mrow;
#pragma unroll
            for (int j = 0; j < 32; ++j) newm = fmaxf(newm, s[j]);
            float alpha = exp2f_fast(mrow - newm);
            lrow *= alpha;
#pragma unroll
            for (int i = 0; i < 40; ++i) o[i] *= alpha;
#pragma unroll
            for (int j = 0; j < 32; ++j) {
                float pj = exp2f_fast(s[j] - newm);
                lrow += pj;
                const float4* vr = (const float4*)&Vs[j * HDIM + doff];
#pragma unroll
                for (int d4 = 0; d4 < 10; ++d4) {
                    float4 vv = vr[d4];
                    o[d4*4+0] += pj * vv.x; o[d4*4+1] += pj * vv.y;
                    o[d4*4+2] += pj * vv.z; o[d4*4+3] += pj * vv.w;
                }
            }
            mrow = newm;
        }
        __syncthreads();
    }

    const float inv = 1.f / lrow;
    const size_t obase = (size_t)(b * SEQ + qi) * HH + h * HDIM + doff;
#pragma unroll
    for (int i = 0; i < 40; ++i) {
        float val = o[i] * inv;
        __nv_bfloat16 hi = __float2bfloat16(val);
        ahi[obase + i] = hi;
        alo[obase + i] = __float2bfloat16(val - __bfloat162float(hi));
    }
}

// ---------------------------------------------------------------------------
// Launch
// ---------------------------------------------------------------------------
extern "C" void kernel_launch(void* const* d_in, const int* in_sizes, int n_in,
                              void* d_out, int out_size)
{
    const float* hidden  = (const float*)d_in[0];
    // d_in[1] = attention_mask: exact additive causal mask; implemented directly.
    const float* scaling = (const float*)d_in[2];
    const float* qkv_w   = (const float*)d_in[3];
    const float* qkv_b   = (const float*)d_in[4];
    const float* o_w     = (const float*)d_in[5];
    const float* o_b     = (const float*)d_in[6];
    float* out = (float*)d_out;

    float *qkv; __nv_bfloat16 *hhi, *hlo, *w1h, *w1l, *w2h, *w2l, *ahi, *alo;
    cudaGetSymbolAddress((void**)&qkv, g_qkv);
    cudaGetSymbolAddress((void**)&hhi, g_h_hi);
    cudaGetSymbolAddress((void**)&hlo, g_h_lo);
    cudaGetSymbolAddress((void**)&w1h, g_w1_hi);
    cudaGetSymbolAddress((void**)&w1l, g_w1_lo);
    cudaGetSymbolAddress((void**)&w2h, g_w2_hi);
    cudaGetSymbolAddress((void**)&w2l, g_w2_lo);
    cudaGetSymbolAddress((void**)&ahi, g_a_hi);
    cudaGetSymbolAddress((void**)&alo, g_a_lo);

    scale_kernel<<<1, 128>>>(scaling);

    {   // hidden -> hi/lo
        int n4 = (MTOT * DMODEL) / 4;
        cvt_split<<<(n4 + 255) / 256, 256>>>(hidden, hhi, hlo, n4);
    }
    {   // qkv_w -> hi/lo
        int n4 = (NQKV * DMODEL) / 4;
        cvt_split<<<(n4 + 255) / 256, 256>>>(qkv_w, w1h, w1l, n4);
    }

    // QKV projection: [8192,1280] @ [3840,1280]^T -> g_qkv (bias + q-scale)
    mma_gemm<0><<<dim3(NQKV / 128, MTOT / 128), 256>>>(
        hhi, hlo, w1h, w1l, qkv_b, qkv, NQKV);

    // Attention -> bf16 hi/lo directly
    flash_kernel<<<dim3(SEQ / 128, BATCH * NHEAD), 256>>>(qkv, ahi, alo);

    {   // o_w -> hi/lo
        int n4 = (DMODEL * HH) / 4;
        cvt_split<<<(n4 + 255) / 256, 256>>>(o_w, w2h, w2l, n4);
    }

    // Output projection: [8192,1280] @ [1280,1280]^T -> out (bias)
    mma_gemm<1><<<dim3(DMODEL / 128, MTOT / 128), 256>>>(
        ahi, alo, w2h, w2l, o_b, out, DMODEL);
}

// round 8
// speedup vs baseline: 2.9536x; 2.2072x over previous
#include <cuda_runtime.h>
#include <cuda_bf16.h>
#include <cstdint>

// Problem constants
#define BATCH 4
#define SEQ   2048
#define DMODEL 1280
#define NHEAD 16
#define HDIM  80
#define MTOT  (BATCH*SEQ)          // 8192
#define NQKV  (3*NHEAD*HDIM)       // 3840
#define HH    (NHEAD*HDIM)         // 1280

// ---------------------------------------------------------------------------
// Scratch (__device__ globals; no allocation anywhere)
// ---------------------------------------------------------------------------
__device__ float         g_qkv[(size_t)MTOT*NQKV];     // [B*S, 3*H*HD] fp32
__device__ __nv_bfloat16 g_h_hi[(size_t)MTOT*DMODEL];
__device__ __nv_bfloat16 g_h_lo[(size_t)MTOT*DMODEL];
__device__ __nv_bfloat16 g_w1_hi[(size_t)NQKV*DMODEL];
__device__ __nv_bfloat16 g_w1_lo[(size_t)NQKV*DMODEL];
__device__ __nv_bfloat16 g_w2_hi[(size_t)DMODEL*HH];
__device__ __nv_bfloat16 g_w2_lo[(size_t)DMODEL*HH];
__device__ __nv_bfloat16 g_a_hi[(size_t)MTOT*HH];
__device__ __nv_bfloat16 g_a_lo[(size_t)MTOT*HH];
__device__ float         g_scale[HDIM];

// ---------------------------------------------------------------------------
// PTX helpers (plain-sm_103 compatible)
// ---------------------------------------------------------------------------
__device__ __forceinline__ uint32_t s2u(const void* p) {
    uint32_t a;
    asm("{ .reg .u64 t; cvta.to.shared.u64 t, %1; cvt.u32.u64 %0, t; }"
        : "=r"(a) : "l"(p));
    return a;
}

__device__ __forceinline__ void cp_async16(uint32_t saddr, const void* gptr) {
    asm volatile("cp.async.cg.shared.global [%0], [%1], 16;"
                 :: "r"(saddr), "l"(gptr) : "memory");
}
__device__ __forceinline__ void cp_commit() {
    asm volatile("cp.async.commit_group;" ::: "memory");
}
template<int N>
__device__ __forceinline__ void cp_wait() {
    asm volatile("cp.async.wait_group %0;" :: "n"(N) : "memory");
}

__device__ __forceinline__ void ldm_x4(uint32_t* r, uint32_t addr) {
    asm volatile("ldmatrix.sync.aligned.m8n8.x4.shared.b16 {%0,%1,%2,%3}, [%4];"
                 : "=r"(r[0]), "=r"(r[1]), "=r"(r[2]), "=r"(r[3]) : "r"(addr));
}
__device__ __forceinline__ void ldm_x4_t(uint32_t* r, uint32_t addr) {
    asm volatile("ldmatrix.sync.aligned.m8n8.x4.trans.shared.b16 {%0,%1,%2,%3}, [%4];"
                 : "=r"(r[0]), "=r"(r[1]), "=r"(r[2]), "=r"(r[3]) : "r"(addr));
}

__device__ __forceinline__ void mma16816(float* c, const uint32_t* a,
                                         uint32_t b0, uint32_t b1) {
    asm volatile(
        "mma.sync.aligned.m16n8k16.row.col.f32.bf16.bf16.f32 "
        "{%0,%1,%2,%3},{%4,%5,%6,%7},{%8,%9},{%0,%1,%2,%3};"
        : "+f"(c[0]), "+f"(c[1]), "+f"(c[2]), "+f"(c[3])
        : "r"(a[0]), "r"(a[1]), "r"(a[2]), "r"(a[3]), "r"(b0), "r"(b1));
}

// pack two fp32 -> bf16x2 (e0 in low half, e1 in high half)
__device__ __forceinline__ uint32_t packbf(float e0, float e1) {
    uint32_t r;
    asm("cvt.rn.bf16x2.f32 %0, %1, %2;" : "=r"(r) : "f"(e1), "f"(e0));
    return r;
}

// truncation split: x = hi + lo, hi = upper-16-bit bf16 bits, lo fp32 residual
__device__ __forceinline__ void split2(float x, uint32_t& hb, float& lf) {
    uint32_t u = __float_as_uint(x) & 0xffff0000u;
    lf = x - __uint_as_float(u);
    hb = u >> 16;
}

// ---------------------------------------------------------------------------
// per-dim query scale (extra log2e: scores live in log2 domain)
// ---------------------------------------------------------------------------
__global__ void scale_kernel(const float* __restrict__ scaling) {
    int i = threadIdx.x;
    if (i < HDIM) {
        float x = scaling[i];
        float sp = (x > 20.f) ? x : log1pf(expf(x));
        g_scale[i] = sp * 1.442695041f * rsqrtf((float)HDIM) * 1.442695041f;
    }
}

// ---------------------------------------------------------------------------
// fp32 -> bf16 hi/lo split (round-to-nearest variant for GEMM operands)
// ---------------------------------------------------------------------------
__global__ void cvt_split(const float* __restrict__ x,
                          __nv_bfloat16* __restrict__ hi,
                          __nv_bfloat16* __restrict__ lo, int n4) {
    int i = blockIdx.x * blockDim.x + threadIdx.x;
    if (i >= n4) return;
    float4 v = ((const float4*)x)[i];
    __nv_bfloat16 h0 = __float2bfloat16(v.x);
    __nv_bfloat16 h1 = __float2bfloat16(v.y);
    __nv_bfloat16 h2 = __float2bfloat16(v.z);
    __nv_bfloat16 h3 = __float2bfloat16(v.w);
    __nv_bfloat162 hh0; hh0.x = h0; hh0.y = h1;
    __nv_bfloat162 hh1; hh1.x = h2; hh1.y = h3;
    __nv_bfloat162 ll0, ll1;
    ll0.x = __float2bfloat16(v.x - __bfloat162float(h0));
    ll0.y = __float2bfloat16(v.y - __bfloat162float(h1));
    ll1.x = __float2bfloat16(v.z - __bfloat162float(h2));
    ll1.y = __float2bfloat16(v.w - __bfloat162float(h3));
    ((__nv_bfloat162*)hi)[2*i]   = hh0;
    ((__nv_bfloat162*)hi)[2*i+1] = hh1;
    ((__nv_bfloat162*)lo)[2*i]   = ll0;
    ((__nv_bfloat162*)lo)[2*i+1] = ll1;
}

// ---------------------------------------------------------------------------
// HMMA GEMM: C = A*B^T + bias (MODE 0: q-scale)
// ---------------------------------------------------------------------------
#define GK     DMODEL        // 1280
#define KCH    (GK/32)       // 40
#define NIT    (3*KCH)       // 120

template<int MODE>
__global__ __launch_bounds__(256)
void mma_gemm(const __nv_bfloat16* __restrict__ Ahi, const __nv_bfloat16* __restrict__ Alo,
              const __nv_bfloat16* __restrict__ Bhi, const __nv_bfloat16* __restrict__ Blo,
              const float* __restrict__ bias, float* __restrict__ dst, int Nld)
{
    __shared__ __align__(16) unsigned char sA[2][128 * 80];
    __shared__ __align__(16) unsigned char sB[2][128 * 80];

    const int tid  = threadIdx.x;
    const int lane = tid & 31;
    const int wid  = tid >> 5;
    const int wm   = wid >> 2;
    const int wn   = wid & 3;
    const int m0   = blockIdx.y * 128;
    const int n0   = blockIdx.x * 128;

    float acc[4][4][4];
#pragma unroll
    for (int a = 0; a < 4; ++a)
#pragma unroll
        for (int b = 0; b < 4; ++b)
#pragma unroll
            for (int c = 0; c < 4; ++c) acc[a][b][c] = 0.f;

    const int lrow = tid >> 2;
    const int lchk = tid & 3;

    auto issue = [&](int cc, int buf) {
        const int seg = cc / KCH;
        const int k0  = (cc % KCH) * 32;
        const __nv_bfloat16* Ap = (seg == 1) ? Alo : Ahi;
        const __nv_bfloat16* Bp = (seg == 2) ? Blo : Bhi;
#pragma unroll
        for (int h = 0; h < 2; ++h) {
            int r = lrow + h * 64;
            cp_async16(s2u(&sA[buf][r * 80 + lchk * 16]),
                       Ap + (size_t)(m0 + r) * GK + k0 + lchk * 8);
            cp_async16(s2u(&sB[buf][r * 80 + lchk * 16]),
                       Bp + (size_t)(n0 + r) * GK + k0 + lchk * 8);
        }
    };

    issue(0, 0);
    cp_commit();

    for (int cc = 0; cc < NIT; ++cc) {
        const int buf = cc & 1;
        if (cc + 1 < NIT) {
            issue(cc + 1, buf ^ 1);
            cp_commit();
            cp_wait<1>();
        } else {
            cp_wait<0>();
        }
        __syncthreads();

#pragma unroll
        for (int ks = 0; ks < 2; ++ks) {
            uint32_t af[4][4];
#pragma unroll
            for (int ms = 0; ms < 4; ++ms) {
                int row  = wm * 64 + ms * 16 + (lane & 15);
                int khal = ks * 16 + (lane >> 4) * 8;
                ldm_x4(af[ms], s2u(&sA[buf][row * 80 + khal * 2]));
            }
            uint32_t bf[2][4];
#pragma unroll
            for (int nb = 0; nb < 2; ++nb) {
                int sel  = lane >> 3;
                int nrow = wn * 32 + nb * 16 + (lane & 7) + (sel >> 1) * 8;
                int khal = ks * 16 + (sel & 1) * 8;
                ldm_x4(bf[nb], s2u(&sB[buf][nrow * 80 + khal * 2]));
            }
#pragma unroll
            for (int ms = 0; ms < 4; ++ms)
#pragma unroll
                for (int ns = 0; ns < 4; ++ns) {
                    const uint32_t* bb = bf[ns >> 1];
                    if (ns & 1) mma16816(acc[ms][ns], af[ms], bb[2], bb[3]);
                    else        mma16816(acc[ms][ns], af[ms], bb[0], bb[1]);
                }
        }
        __syncthreads();
    }

    const int qr = lane >> 2;
    const int qc = lane & 3;
#pragma unroll
    for (int ms = 0; ms < 4; ++ms) {
        int mrow = m0 + wm * 64 + ms * 16 + qr;
#pragma unroll
        for (int ns = 0; ns < 4; ++ns) {
            int ncol = n0 + wn * 32 + ns * 8 + qc * 2;
            float b0 = bias[ncol], b1 = bias[ncol + 1];
            float s0 = 1.f, s1 = 1.f;
            if (MODE == 0 && ncol < HH) {
                int d = ncol % HDIM;
                s0 = g_scale[d];
                s1 = g_scale[d + 1];
            }
            float2 v0, v1;
            v0.x = (acc[ms][ns][0] + b0) * s0;
            v0.y = (acc[ms][ns][1] + b1) * s1;
            v1.x = (acc[ms][ns][2] + b0) * s0;
            v1.y = (acc[ms][ns][3] + b1) * s1;
            *(float2*)&dst[(size_t)mrow * Nld + ncol]       = v0;
            *(float2*)&dst[(size_t)(mrow + 8) * Nld + ncol] = v1;
        }
    }
}

// ---------------------------------------------------------------------------
// exp2 on the FMA pipe (no MUFU); args always <= 0 here
// ---------------------------------------------------------------------------
__device__ __forceinline__ float exp2f_fast(float x) {
    x = fmaxf(x, -126.f);
    float t = rintf(x);
    float f = x - t;
    float p = 1.3333558e-3f;
    p = fmaf(p, f, 9.6181291e-3f);
    p = fmaf(p, f, 5.5504109e-2f);
    p = fmaf(p, f, 2.4022651e-1f);
    p = fmaf(p, f, 6.9314718e-1f);
    p = fmaf(p, f, 1.0f);
    return __int_as_float(__float_as_int(p) + (((int)t) << 23));
}

// ---------------------------------------------------------------------------
// Tensor-core flash attention (causal, log2-domain softmax).
// Block: 128 q-rows of one (b,h), 8 warps x 16 rows. K tiles of 64 keys.
// QK^T: bf16 hi/lo (hh+lh+hl). P*V: PH*VH + PL*VH + PH*VL (V now hi/lo!).
// ---------------------------------------------------------------------------
#define STR 88   // bf16 elements per smem row (176B, conflict-free for ldmatrix)

__global__ __launch_bounds__(256)
void flash_tc(const float* __restrict__ qkv,
              __nv_bfloat16* __restrict__ ahi,
              __nv_bfloat16* __restrict__ alo)
{
    __shared__ union {
        struct { __nv_bfloat16 h[128*STR]; __nv_bfloat16 l[128*STR]; } q;
        struct { __nv_bfloat16 kh[64*STR]; __nv_bfloat16 kl[64*STR];
                 __nv_bfloat16 vh[64*STR]; __nv_bfloat16 vl[64*STR]; } kv;
    } sm;

    const int tid  = threadIdx.x;
    const int lane = tid & 31;
    const int wm   = tid >> 5;
    const int qb   = blockIdx.x;
    const int bh   = blockIdx.y;
    const int b    = bh >> 4, h = bh & 15;

    // ---- stage Q (pre-scaled fp32 -> bf16 hi/lo) ----
    {
        int row = tid >> 1, half = tid & 1;
        const float* qp = qkv + (size_t)(b*SEQ + qb*128 + row)*NQKV + h*HDIM + half*40;
        uint32_t* dh = (uint32_t*)&sm.q.h[row*STR + half*40];
        uint32_t* dl = (uint32_t*)&sm.q.l[row*STR + half*40];
#pragma unroll
        for (int i = 0; i < 10; ++i) {
            float4 v = *(const float4*)(qp + i*4);
            uint32_t h0,h1,h2,h3; float l0,l1,l2,l3;
            split2(v.x,h0,l0); split2(v.y,h1,l1);
            split2(v.z,h2,l2); split2(v.w,h3,l3);
            dh[i*2]   = h0 | (h1 << 16);
            dh[i*2+1] = h2 | (h3 << 16);
            dl[i*2]   = packbf(l0, l1);
            dl[i*2+1] = packbf(l2, l3);
        }
    }
    __syncthreads();

    uint32_t QH[5][4], QL[5][4];
    {
        int r = wm*16 + (lane & 15);
        int ko = (lane >> 4) * 8;
#pragma unroll
        for (int kf = 0; kf < 5; ++kf) {
            ldm_x4(QH[kf], s2u(&sm.q.h[r*STR + kf*16 + ko]));
            ldm_x4(QL[kf], s2u(&sm.q.l[r*STR + kf*16 + ko]));
        }
    }
    __syncthreads();   // done with q region before kv overwrites it

    float O[10][4];
#pragma unroll
    for (int i = 0; i < 10; ++i)
#pragma unroll
        for (int j = 0; j < 4; ++j) O[i][j] = 0.f;
    float m0 = -1e30f, m1 = -1e30f, l0 = 0.f, l1 = 0.f;

    const int ntiles = qb*2 + 2;
    const int qrow = qb*128 + wm*16 + (lane >> 2);   // row0; row1 = qrow+8

    for (int t = 0; t < ntiles; ++t) {
        // ---- load K/V tile (64 keys), both hi/lo ----
        {
            int r = tid >> 2, q4 = tid & 3;
            const float* kp = qkv + (size_t)(b*SEQ + t*64 + r)*NQKV + HH + h*HDIM + q4*20;
            const float* vp = kp + HH;
            uint32_t* kh = (uint32_t*)&sm.kv.kh[r*STR + q4*20];
            uint32_t* kl = (uint32_t*)&sm.kv.kl[r*STR + q4*20];
            uint32_t* vh = (uint32_t*)&sm.kv.vh[r*STR + q4*20];
            uint32_t* vl = (uint32_t*)&sm.kv.vl[r*STR + q4*20];
#pragma unroll
            for (int i = 0; i < 5; ++i) {
                float4 kq = *(const float4*)(kp + i*4);
                uint32_t h0,h1,h2,h3; float f0,f1,f2,f3;
                split2(kq.x,h0,f0); split2(kq.y,h1,f1);
                split2(kq.z,h2,f2); split2(kq.w,h3,f3);
                kh[i*2]   = h0 | (h1 << 16);
                kh[i*2+1] = h2 | (h3 << 16);
                kl[i*2]   = packbf(f0, f1);
                kl[i*2+1] = packbf(f2, f3);
                float4 vq = *(const float4*)(vp + i*4);
                split2(vq.x,h0,f0); split2(vq.y,h1,f1);
                split2(vq.z,h2,f2); split2(vq.w,h3,f3);
                vh[i*2]   = h0 | (h1 << 16);
                vh[i*2+1] = h2 | (h3 << 16);
                vl[i*2]   = packbf(f0, f1);
                vl[i*2+1] = packbf(f2, f3);
            }
        }
        __syncthreads();

        const bool active = (t*64) <= (qb*128 + wm*16 + 15);
        if (active) {
            float S[8][4];
#pragma unroll
            for (int i = 0; i < 8; ++i)
#pragma unroll
                for (int j = 0; j < 4; ++j) S[i][j] = 0.f;

            // ---- S = Q K^T (hh + lh + hl) ----
#pragma unroll
            for (int kf = 0; kf < 5; ++kf) {
                const int sel  = lane >> 3;
                const int koff = kf*16 + (sel & 1)*8;
#pragma unroll
                for (int g = 0; g < 4; ++g) {
                    uint32_t bh_[4], bl_[4];
                    int krow = g*16 + (lane & 7) + (sel >> 1)*8;
                    ldm_x4(bh_, s2u(&sm.kv.kh[krow*STR + koff]));
                    ldm_x4(bl_, s2u(&sm.kv.kl[krow*STR + koff]));
                    mma16816(S[2*g],   QH[kf], bh_[0], bh_[1]);
                    mma16816(S[2*g+1], QH[kf], bh_[2], bh_[3]);
                    mma16816(S[2*g],   QL[kf], bh_[0], bh_[1]);
                    mma16816(S[2*g+1], QL[kf], bh_[2], bh_[3]);
                    mma16816(S[2*g],   QH[kf], bl_[0], bl_[1]);
                    mma16816(S[2*g+1], QH[kf], bl_[2], bl_[3]);
                }
            }

            // ---- causal mask (diagonal tiles only) ----
            if (t*64 + 63 > qb*128 + wm*16) {
#pragma unroll
                for (int nt = 0; nt < 8; ++nt) {
                    int j = t*64 + nt*8 + (lane & 3)*2;
                    if (j     > qrow)     S[nt][0] = -1e30f;
                    if (j + 1 > qrow)     S[nt][1] = -1e30f;
                    if (j     > qrow + 8) S[nt][2] = -1e30f;
                    if (j + 1 > qrow + 8) S[nt][3] = -1e30f;
                }
            }

            // ---- online softmax ----
            float rm0 = -1e30f, rm1 = -1e30f;
#pragma unroll
            for (int nt = 0; nt < 8; ++nt) {
                rm0 = fmaxf(rm0, fmaxf(S[nt][0], S[nt][1]));
                rm1 = fmaxf(rm1, fmaxf(S[nt][2], S[nt][3]));
            }
            rm0 = fmaxf(rm0, __shfl_xor_sync(0xffffffffu, rm0, 1));
            rm0 = fmaxf(rm0, __shfl_xor_sync(0xffffffffu, rm0, 2));
            rm1 = fmaxf(rm1, __shfl_xor_sync(0xffffffffu, rm1, 1));
            rm1 = fmaxf(rm1, __shfl_xor_sync(0xffffffffu, rm1, 2));

            float nm0 = fmaxf(m0, rm0), nm1 = fmaxf(m1, rm1);
            float a0 = exp2f_fast(m0 - nm0), a1 = exp2f_fast(m1 - nm1);
            m0 = nm0; m1 = nm1;
#pragma unroll
            for (int nt = 0; nt < 10; ++nt) {
                O[nt][0] *= a0; O[nt][1] *= a0;
                O[nt][2] *= a1; O[nt][3] *= a1;
            }
            float s0 = 0.f, s1 = 0.f;
#pragma unroll
            for (int nt = 0; nt < 8; ++nt) {
                S[nt][0] = exp2f_fast(S[nt][0] - nm0); s0 += S[nt][0];
                S[nt][1] = exp2f_fast(S[nt][1] - nm0); s0 += S[nt][1];
                S[nt][2] = exp2f_fast(S[nt][2] - nm1); s1 += S[nt][2];
                S[nt][3] = exp2f_fast(S[nt][3] - nm1); s1 += S[nt][3];
            }
            s0 += __shfl_xor_sync(0xffffffffu, s0, 1);
            s0 += __shfl_xor_sync(0xffffffffu, s0, 2);
            s1 += __shfl_xor_sync(0xffffffffu, s1, 1);
            s1 += __shfl_xor_sync(0xffffffffu, s1, 2);
            l0 = l0*a0 + s0;
            l1 = l1*a1 + s1;

            // ---- P -> A fragments (hi/lo, in-register) ----
            uint32_t PH[4][4], PL[4][4];
#pragma unroll
            for (int g = 0; g < 4; ++g) {
                uint32_t hb[8]; float lf[8];
                split2(S[2*g][0], hb[0], lf[0]);  split2(S[2*g][1], hb[1], lf[1]);
                split2(S[2*g][2], hb[2], lf[2]);  split2(S[2*g][3], hb[3], lf[3]);
                split2(S[2*g+1][0], hb[4], lf[4]); split2(S[2*g+1][1], hb[5], lf[5]);
                split2(S[2*g+1][2], hb[6], lf[6]); split2(S[2*g+1][3], hb[7], lf[7]);
                PH[g][0] = hb[0] | (hb[1] << 16);
                PH[g][1] = hb[2] | (hb[3] << 16);
                PH[g][2] = hb[4] | (hb[5] << 16);
                PH[g][3] = hb[6] | (hb[7] << 16);
                PL[g][0] = packbf(lf[0], lf[1]);
                PL[g][1] = packbf(lf[2], lf[3]);
                PL[g][2] = packbf(lf[4], lf[5]);
                PL[g][3] = packbf(lf[6], lf[7]);
            }

            // ---- O += PH*VH + PL*VH + PH*VL ----
            const int sel = lane >> 3;
#pragma unroll
            for (int g = 0; g < 4; ++g) {
                int krow = g*16 + (lane & 7) + (sel & 1)*8;
#pragma unroll
                for (int np = 0; np < 5; ++np) {
                    uint32_t bv[4], bw[4];
                    int noff = np*16 + (sel >> 1)*8;
                    ldm_x4_t(bv, s2u(&sm.kv.vh[krow*STR + noff]));
                    ldm_x4_t(bw, s2u(&sm.kv.vl[krow*STR + noff]));
                    mma16816(O[2*np],   PH[g], bv[0], bv[1]);
                    mma16816(O[2*np],   PL[g], bv[0], bv[1]);
                    mma16816(O[2*np],   PH[g], bw[0], bw[1]);
                    mma16816(O[2*np+1], PH[g], bv[2], bv[3]);
                    mma16816(O[2*np+1], PL[g], bv[2], bv[3]);
                    mma16816(O[2*np+1], PH[g], bw[2], bw[3]);
                }
            }
        }
        __syncthreads();
    }

    // ---- epilogue: normalize, write bf16 hi/lo ----
    const float i0 = 1.f / l0, i1 = 1.f / l1;
    const size_t base0 = (size_t)(b*SEQ + qrow) * HH + h * HDIM;
    const size_t base1 = base0 + (size_t)8 * HH;
#pragma unroll
    for (int nt = 0; nt < 10; ++nt) {
        int d = nt*8 + (lane & 3)*2;
        {
            float v0 = O[nt][0]*i0, v1 = O[nt][1]*i0;
            uint32_t h0,h1; float f0,f1;
            split2(v0,h0,f0); split2(v1,h1,f1);
            *(uint32_t*)&ahi[base0 + d] = h0 | (h1 << 16);
            *(uint32_t*)&alo[base0 + d] = packbf(f0, f1);
        }
        {
            float v0 = O[nt][2]*i1, v1 = O[nt][3]*i1;
            uint32_t h0,h1; float f0,f1;
            split2(v0,h0,f0); split2(v1,h1,f1);
            *(uint32_t*)&ahi[base1 + d] = h0 | (h1 << 16);
            *(uint32_t*)&alo[base1 + d] = packbf(f0, f1);
        }
    }
}

// ---------------------------------------------------------------------------
// Launch
// ---------------------------------------------------------------------------
extern "C" void kernel_launch(void* const* d_in, const int* in_sizes, int n_in,
                              void* d_out, int out_size)
{
    const float* hidden  = (const float*)d_in[0];
    // d_in[1] = attention_mask: exact additive causal mask; implemented directly.
    const float* scaling = (const float*)d_in[2];
    const float* qkv_w   = (const float*)d_in[3];
    const float* qkv_b   = (const float*)d_in[4];
    const float* o_w     = (const float*)d_in[5];
    const float* o_b     = (const float*)d_in[6];
    float* out = (float*)d_out;

    float *qkv; __nv_bfloat16 *hhi, *hlo, *w1h, *w1l, *w2h, *w2l, *ahi, *alo;
    cudaGetSymbolAddress((void**)&qkv, g_qkv);
    cudaGetSymbolAddress((void**)&hhi, g_h_hi);
    cudaGetSymbolAddress((void**)&hlo, g_h_lo);
    cudaGetSymbolAddress((void**)&w1h, g_w1_hi);
    cudaGetSymbolAddress((void**)&w1l, g_w1_lo);
    cudaGetSymbolAddress((void**)&w2h, g_w2_hi);
    cudaGetSymbolAddress((void**)&w2l, g_w2_lo);
    cudaGetSymbolAddress((void**)&ahi, g_a_hi);
    cudaGetSymbolAddress((void**)&alo, g_a_lo);

    scale_kernel<<<1, 128>>>(scaling);

    {   // hidden -> hi/lo
        int n4 = (MTOT * DMODEL) / 4;
        cvt_split<<<(n4 + 255) / 256, 256>>>(hidden, hhi, hlo, n4);
    }
    {   // qkv_w -> hi/lo
        int n4 = (NQKV * DMODEL) / 4;
        cvt_split<<<(n4 + 255) / 256, 256>>>(qkv_w, w1h, w1l, n4);
    }

    // QKV projection: [8192,1280] @ [3840,1280]^T -> g_qkv (bias + q-scale)
    mma_gemm<0><<<dim3(NQKV / 128, MTOT / 128), 256>>>(
        hhi, hlo, w1h, w1l, qkv_b, qkv, NQKV);

    // Tensor-core flash attention -> bf16 hi/lo
    flash_tc<<<dim3(SEQ / 128, BATCH * NHEAD), 256>>>(qkv, ahi, alo);

    {   // o_w -> hi/lo
        int n4 = (DMODEL * HH) / 4;
        cvt_split<<<(n4 + 255) / 256, 256>>>(o_w, w2h, w2l, n4);
    }

    // Output projection: [8192,1280] @ [1280,1280]^T -> out (bias)
    mma_gemm<1><<<dim3(DMODEL / 128, MTOT / 128), 256>>>(
        ahi, alo, w2h, w2l, o_b, out, DMODEL);
}

// round 9
// speedup vs baseline: 3.0781x; 1.0421x over previous
#include <cuda_runtime.h>
#include <cuda_bf16.h>
#include <cstdint>

// Problem constants
#define BATCH 4
#define SEQ   2048
#define DMODEL 1280
#define NHEAD 16
#define HDIM  80
#define MTOT  (BATCH*SEQ)          // 8192
#define NQKV  (3*NHEAD*HDIM)       // 3840
#define HH    (NHEAD*HDIM)         // 1280

// ---------------------------------------------------------------------------
// Scratch (__device__ globals; no allocation anywhere)
// ---------------------------------------------------------------------------
__device__ float         g_qkv[(size_t)MTOT*NQKV];     // [B*S, 3*H*HD] fp32
__device__ __nv_bfloat16 g_h_hi[(size_t)MTOT*DMODEL];
__device__ __nv_bfloat16 g_h_lo[(size_t)MTOT*DMODEL];
__device__ __nv_bfloat16 g_w1_hi[(size_t)NQKV*DMODEL];
__device__ __nv_bfloat16 g_w1_lo[(size_t)NQKV*DMODEL];
__device__ __nv_bfloat16 g_w2_hi[(size_t)DMODEL*HH];
__device__ __nv_bfloat16 g_w2_lo[(size_t)DMODEL*HH];
__device__ __nv_bfloat16 g_a_hi[(size_t)MTOT*HH];
__device__ __nv_bfloat16 g_a_lo[(size_t)MTOT*HH];
__device__ float         g_scale[HDIM];

// ---------------------------------------------------------------------------
// PTX helpers (plain-sm_103 compatible)
// ---------------------------------------------------------------------------
__device__ __forceinline__ uint32_t s2u(const void* p) {
    uint32_t a;
    asm("{ .reg .u64 t; cvta.to.shared.u64 t, %1; cvt.u32.u64 %0, t; }"
        : "=r"(a) : "l"(p));
    return a;
}

__device__ __forceinline__ void cp_async16(uint32_t saddr, const void* gptr) {
    asm volatile("cp.async.cg.shared.global [%0], [%1], 16;"
                 :: "r"(saddr), "l"(gptr) : "memory");
}
__device__ __forceinline__ void cp_commit() {
    asm volatile("cp.async.commit_group;" ::: "memory");
}
template<int N>
__device__ __forceinline__ void cp_wait() {
    asm volatile("cp.async.wait_group %0;" :: "n"(N) : "memory");
}

__device__ __forceinline__ void ldm_x4(uint32_t* r, uint32_t addr) {
    asm volatile("ldmatrix.sync.aligned.m8n8.x4.shared.b16 {%0,%1,%2,%3}, [%4];"
                 : "=r"(r[0]), "=r"(r[1]), "=r"(r[2]), "=r"(r[3]) : "r"(addr));
}
__device__ __forceinline__ void ldm_x4_t(uint32_t* r, uint32_t addr) {
    asm volatile("ldmatrix.sync.aligned.m8n8.x4.trans.shared.b16 {%0,%1,%2,%3}, [%4];"
                 : "=r"(r[0]), "=r"(r[1]), "=r"(r[2]), "=r"(r[3]) : "r"(addr));
}

__device__ __forceinline__ void mma16816(float* c, const uint32_t* a,
                                         uint32_t b0, uint32_t b1) {
    asm volatile(
        "mma.sync.aligned.m16n8k16.row.col.f32.bf16.bf16.f32 "
        "{%0,%1,%2,%3},{%4,%5,%6,%7},{%8,%9},{%0,%1,%2,%3};"
        : "+f"(c[0]), "+f"(c[1]), "+f"(c[2]), "+f"(c[3])
        : "r"(a[0]), "r"(a[1]), "r"(a[2]), "r"(a[3]), "r"(b0), "r"(b1));
}

// pack two fp32 -> bf16x2 (e0 in low half, e1 in high half)
__device__ __forceinline__ uint32_t packbf(float e0, float e1) {
    uint32_t r;
    asm("cvt.rn.bf16x2.f32 %0, %1, %2;" : "=r"(r) : "f"(e1), "f"(e0));
    return r;
}

// truncation split: x = hi + lo, hi = upper-16-bit bf16 bits, lo fp32 residual
__device__ __forceinline__ void split2(float x, uint32_t& hb, float& lf) {
    uint32_t u = __float_as_uint(x) & 0xffff0000u;
    lf = x - __uint_as_float(u);
    hb = u >> 16;
}

// ---------------------------------------------------------------------------
// per-dim query scale (extra log2e: scores live in log2 domain)
// ---------------------------------------------------------------------------
__global__ void scale_kernel(const float* __restrict__ scaling) {
    int i = threadIdx.x;
    if (i < HDIM) {
        float x = scaling[i];
        float sp = (x > 20.f) ? x : log1pf(expf(x));
        g_scale[i] = sp * 1.442695041f * rsqrtf((float)HDIM) * 1.442695041f;
    }
}

// ---------------------------------------------------------------------------
// fp32 -> bf16 hi/lo split
// ---------------------------------------------------------------------------
__global__ void cvt_split(const float* __restrict__ x,
                          __nv_bfloat16* __restrict__ hi,
                          __nv_bfloat16* __restrict__ lo, int n4) {
    int i = blockIdx.x * blockDim.x + threadIdx.x;
    if (i >= n4) return;
    float4 v = ((const float4*)x)[i];
    __nv_bfloat16 h0 = __float2bfloat16(v.x);
    __nv_bfloat16 h1 = __float2bfloat16(v.y);
    __nv_bfloat16 h2 = __float2bfloat16(v.z);
    __nv_bfloat16 h3 = __float2bfloat16(v.w);
    __nv_bfloat162 hh0; hh0.x = h0; hh0.y = h1;
    __nv_bfloat162 hh1; hh1.x = h2; hh1.y = h3;
    __nv_bfloat162 ll0, ll1;
    ll0.x = __float2bfloat16(v.x - __bfloat162float(h0));
    ll0.y = __float2bfloat16(v.y - __bfloat162float(h1));
    ll1.x = __float2bfloat16(v.z - __bfloat162float(h2));
    ll1.y = __float2bfloat16(v.w - __bfloat162float(h3));
    ((__nv_bfloat162*)hi)[2*i]   = hh0;
    ((__nv_bfloat162*)hi)[2*i+1] = hh1;
    ((__nv_bfloat162*)lo)[2*i]   = ll0;
    ((__nv_bfloat162*)lo)[2*i+1] = ll1;
}

// ---------------------------------------------------------------------------
// HMMA GEMM: C = A*B^T + bias (MODE 0: q-scale)
// 4-stage cp.async pipeline, ONE __syncthreads per K-chunk iteration.
// ---------------------------------------------------------------------------
#define GK      DMODEL       // 1280
#define KCH     (GK/32)      // 40
#define NIT     (3*KCH)      // 120
#define STG_B   20480        // bytes per pipeline stage (A 10240 + B 10240)
#define GSMEM   (4*STG_B)    // 81920

template<int MODE>
__global__ __launch_bounds__(256)
void mma_gemm(const __nv_bfloat16* __restrict__ Ahi, const __nv_bfloat16* __restrict__ Alo,
              const __nv_bfloat16* __restrict__ Bhi, const __nv_bfloat16* __restrict__ Blo,
              const float* __restrict__ bias, float* __restrict__ dst, int Nld)
{
    extern __shared__ __align__(16) unsigned char dynsm[];

    const int tid  = threadIdx.x;
    const int lane = tid & 31;
    const int wid  = tid >> 5;
    const int wm   = wid >> 2;
    const int wn   = wid & 3;
    const int m0   = blockIdx.y * 128;
    const int n0   = blockIdx.x * 128;

    float acc[4][4][4];
#pragma unroll
    for (int a = 0; a < 4; ++a)
#pragma unroll
        for (int b = 0; b < 4; ++b)
#pragma unroll
            for (int c = 0; c < 4; ++c) acc[a][b][c] = 0.f;

    const int lrow = tid >> 2;
    const int lchk = tid & 3;
    const uint32_t smem_u = s2u(dynsm);

    auto issue = [&](int cc, int stg) {
        const int seg = cc / KCH;
        const int k0  = (cc % KCH) * 32;
        const __nv_bfloat16* Ap = (seg == 1) ? Alo : Ahi;
        const __nv_bfloat16* Bp = (seg == 2) ? Blo : Bhi;
        uint32_t sa = smem_u + stg * STG_B;
        uint32_t sb = sa + 10240;
#pragma unroll
        for (int h = 0; h < 2; ++h) {
            int r = lrow + h * 64;
            cp_async16(sa + r * 80 + lchk * 16,
                       Ap + (size_t)(m0 + r) * GK + k0 + lchk * 8);
            cp_async16(sb + r * 80 + lchk * 16,
                       Bp + (size_t)(n0 + r) * GK + k0 + lchk * 8);
        }
    };

    // prologue: stages 0..2 in flight
#pragma unroll
    for (int s = 0; s < 3; ++s) { issue(s, s); cp_commit(); }

    for (int cc = 0; cc < NIT; ++cc) {
        const int stg = cc & 3;
        cp_wait<2>();          // stage cc resident
        __syncthreads();       // CTA-wide visibility + buffer-reuse safety
        if (cc + 3 < NIT) issue(cc + 3, (cc + 3) & 3);
        cp_commit();           // empty groups near the tail keep counting simple

        uint32_t sa = smem_u + stg * STG_B;
        uint32_t sb = sa + 10240;
#pragma unroll
        for (int ks = 0; ks < 2; ++ks) {
            uint32_t af[4][4];
#pragma unroll
            for (int ms = 0; ms < 4; ++ms) {
                int row  = wm * 64 + ms * 16 + (lane & 15);
                int khal = ks * 16 + (lane >> 4) * 8;
                ldm_x4(af[ms], sa + row * 80 + khal * 2);
            }
            uint32_t bf[2][4];
#pragma unroll
            for (int nb = 0; nb < 2; ++nb) {
                int sel  = lane >> 3;
                int nrow = wn * 32 + nb * 16 + (lane & 7) + (sel >> 1) * 8;
                int khal = ks * 16 + (sel & 1) * 8;
                ldm_x4(bf[nb], sb + nrow * 80 + khal * 2);
            }
#pragma unroll
            for (int ms = 0; ms < 4; ++ms)
#pragma unroll
                for (int ns = 0; ns < 4; ++ns) {
                    const uint32_t* bb = bf[ns >> 1];
                    if (ns & 1) mma16816(acc[ms][ns], af[ms], bb[2], bb[3]);
                    else        mma16816(acc[ms][ns], af[ms], bb[0], bb[1]);
                }
        }
    }

    const int qr = lane >> 2;
    const int qc = lane & 3;
#pragma unroll
    for (int ms = 0; ms < 4; ++ms) {
        int mrow = m0 + wm * 64 + ms * 16 + qr;
#pragma unroll
        for (int ns = 0; ns < 4; ++ns) {
            int ncol = n0 + wn * 32 + ns * 8 + qc * 2;
            float b0 = bias[ncol], b1 = bias[ncol + 1];
            float s0 = 1.f, s1 = 1.f;
            if (MODE == 0 && ncol < HH) {
                int d = ncol % HDIM;
                s0 = g_scale[d];
                s1 = g_scale[d + 1];
            }
            float2 v0, v1;
            v0.x = (acc[ms][ns][0] + b0) * s0;
            v0.y = (acc[ms][ns][1] + b1) * s1;
            v1.x = (acc[ms][ns][2] + b0) * s0;
            v1.y = (acc[ms][ns][3] + b1) * s1;
            *(float2*)&dst[(size_t)mrow * Nld + ncol]       = v0;
            *(float2*)&dst[(size_t)(mrow + 8) * Nld + ncol] = v1;
        }
    }
}

// ---------------------------------------------------------------------------
// exp2 on the FMA pipe (no MUFU); args always <= 0 here
// ---------------------------------------------------------------------------
__device__ __forceinline__ float exp2f_fast(float x) {
    x = fmaxf(x, -126.f);
    float t = rintf(x);
    float f = x - t;
    float p = 1.3333558e-3f;
    p = fmaf(p, f, 9.6181291e-3f);
    p = fmaf(p, f, 5.5504109e-2f);
    p = fmaf(p, f, 2.4022651e-1f);
    p = fmaf(p, f, 6.9314718e-1f);
    p = fmaf(p, f, 1.0f);
    return __int_as_float(__float_as_int(p) + (((int)t) << 23));
}

// ---------------------------------------------------------------------------
// Tensor-core flash attention (causal, log2-domain softmax).
// Register-prefetch of the next K/V tile overlaps LDG with the mma block.
// ---------------------------------------------------------------------------
#define STR 88   // bf16 elements per smem row (176B, conflict-free ldmatrix)

__global__ __launch_bounds__(256)
void flash_tc(const float* __restrict__ qkv,
              __nv_bfloat16* __restrict__ ahi,
              __nv_bfloat16* __restrict__ alo)
{
    __shared__ union {
        struct { __nv_bfloat16 h[128*STR]; __nv_bfloat16 l[128*STR]; } q;
        struct { __nv_bfloat16 kh[64*STR]; __nv_bfloat16 kl[64*STR];
                 __nv_bfloat16 vh[64*STR]; __nv_bfloat16 vl[64*STR]; } kv;
    } sm;

    const int tid  = threadIdx.x;
    const int lane = tid & 31;
    const int wm   = tid >> 5;
    const int qb   = blockIdx.x;
    const int bh   = blockIdx.y;
    const int b    = bh >> 4, h = bh & 15;

    // ---- stage Q (pre-scaled fp32 -> bf16 hi/lo) ----
    {
        int row = tid >> 1, half = tid & 1;
        const float* qp = qkv + (size_t)(b*SEQ + qb*128 + row)*NQKV + h*HDIM + half*40;
        uint32_t* dh = (uint32_t*)&sm.q.h[row*STR + half*40];
        uint32_t* dl = (uint32_t*)&sm.q.l[row*STR + half*40];
#pragma unroll
        for (int i = 0; i < 10; ++i) {
            float4 v = *(const float4*)(qp + i*4);
            uint32_t h0,h1,h2,h3; float l0,l1,l2,l3;
            split2(v.x,h0,l0); split2(v.y,h1,l1);
            split2(v.z,h2,l2); split2(v.w,h3,l3);
            dh[i*2]   = h0 | (h1 << 16);
            dh[i*2+1] = h2 | (h3 << 16);
            dl[i*2]   = packbf(l0, l1);
            dl[i*2+1] = packbf(l2, l3);
        }
    }
    __syncthreads();

    uint32_t QH[5][4], QL[5][4];
    {
        int r = wm*16 + (lane & 15);
        int ko = (lane >> 4) * 8;
#pragma unroll
        for (int kf = 0; kf < 5; ++kf) {
            ldm_x4(QH[kf], s2u(&sm.q.h[r*STR + kf*16 + ko]));
            ldm_x4(QL[kf], s2u(&sm.q.l[r*STR + kf*16 + ko]));
        }
    }
    __syncthreads();   // done with q region before kv overwrites it

    float O[10][4];
#pragma unroll
    for (int i = 0; i < 10; ++i)
#pragma unroll
        for (int j = 0; j < 4; ++j) O[i][j] = 0.f;
    float m0 = -1e30f, m1 = -1e30f, l0 = 0.f, l1 = 0.f;

    const int ntiles = qb*2 + 2;
    const int qrow = qb*128 + wm*16 + (lane >> 2);   // row0; row1 = qrow+8

    const int ldr = tid >> 2, ldq = tid & 3;
    const float* kb0 = qkv + (size_t)b*SEQ*NQKV + HH + h*HDIM + ldq*20;

    float4 kreg[5], vreg[5];
    {   // prefetch tile 0
        const float* kp = kb0 + (size_t)ldr * NQKV;
        const float* vp = kp + HH;
#pragma unroll
        for (int i = 0; i < 5; ++i) {
            kreg[i] = *(const float4*)(kp + i*4);
            vreg[i] = *(const float4*)(vp + i*4);
        }
    }

    for (int t = 0; t < ntiles; ++t) {
        // ---- convert + store prefetched K/V tile (hi/lo) ----
        {
            uint32_t* kh = (uint32_t*)&sm.kv.kh[ldr*STR + ldq*20];
            uint32_t* kl = (uint32_t*)&sm.kv.kl[ldr*STR + ldq*20];
            uint32_t* vh = (uint32_t*)&sm.kv.vh[ldr*STR + ldq*20];
            uint32_t* vl = (uint32_t*)&sm.kv.vl[ldr*STR + ldq*20];
#pragma unroll
            for (int i = 0; i < 5; ++i) {
                uint32_t h0,h1,h2,h3; float f0,f1,f2,f3;
                split2(kreg[i].x,h0,f0); split2(kreg[i].y,h1,f1);
                split2(kreg[i].z,h2,f2); split2(kreg[i].w,h3,f3);
                kh[i*2]   = h0 | (h1 << 16);
                kh[i*2+1] = h2 | (h3 << 16);
                kl[i*2]   = packbf(f0, f1);
                kl[i*2+1] = packbf(f2, f3);
                split2(vreg[i].x,h0,f0); split2(vreg[i].y,h1,f1);
                split2(vreg[i].z,h2,f2); split2(vreg[i].w,h3,f3);
                vh[i*2]   = h0 | (h1 << 16);
                vh[i*2+1] = h2 | (h3 << 16);
                vl[i*2]   = packbf(f0, f1);
                vl[i*2+1] = packbf(f2, f3);
            }
        }
        __syncthreads();

        // ---- prefetch next tile while mma block runs ----
        if (t + 1 < ntiles) {
            const float* kp = kb0 + (size_t)((t+1)*64 + ldr) * NQKV;
            const float* vp = kp + HH;
#pragma unroll
            for (int i = 0; i < 5; ++i) {
                kreg[i] = *(const float4*)(kp + i*4);
                vreg[i] = *(const float4*)(vp + i*4);
            }
        }

        const bool active = (t*64) <= (qb*128 + wm*16 + 15);
        if (active) {
            float S[8][4];
#pragma unroll
            for (int i = 0; i < 8; ++i)
#pragma unroll
                for (int j = 0; j < 4; ++j) S[i][j] = 0.f;

            // ---- S = Q K^T (hh + lh + hl) ----
#pragma unroll
            for (int kf = 0; kf < 5; ++kf) {
                const int sel  = lane >> 3;
                const int koff = kf*16 + (sel & 1)*8;
#pragma unroll
                for (int g = 0; g < 4; ++g) {
                    uint32_t bh_[4], bl_[4];
                    int krow = g*16 + (lane & 7) + (sel >> 1)*8;
                    ldm_x4(bh_, s2u(&sm.kv.kh[krow*STR + koff]));
                    ldm_x4(bl_, s2u(&sm.kv.kl[krow*STR + koff]));
                    mma16816(S[2*g],   QH[kf], bh_[0], bh_[1]);
                    mma16816(S[2*g+1], QH[kf], bh_[2], bh_[3]);
                    mma16816(S[2*g],   QL[kf], bh_[0], bh_[1]);
                    mma16816(S[2*g+1], QL[kf], bh_[2], bh_[3]);
                    mma16816(S[2*g],   QH[kf], bl_[0], bl_[1]);
                    mma16816(S[2*g+1], QH[kf], bl_[2], bl_[3]);
                }
            }

            // ---- causal mask (diagonal tiles only) ----
            if (t*64 + 63 > qb*128 + wm*16) {
#pragma unroll
                for (int nt = 0; nt < 8; ++nt) {
                    int j = t*64 + nt*8 + (lane & 3)*2;
                    if (j     > qrow)     S[nt][0] = -1e30f;
                    if (j + 1 > qrow)     S[nt][1] = -1e30f;
                    if (j     > qrow + 8) S[nt][2] = -1e30f;
                    if (j + 1 > qrow + 8) S[nt][3] = -1e30f;
                }
            }

            // ---- online softmax ----
            float rm0 = -1e30f, rm1 = -1e30f;
#pragma unroll
            for (int nt = 0; nt < 8; ++nt) {
                rm0 = fmaxf(rm0, fmaxf(S[nt][0], S[nt][1]));
                rm1 = fmaxf(rm1, fmaxf(S[nt][2], S[nt][3]));
            }
            rm0 = fmaxf(rm0, __shfl_xor_sync(0xffffffffu, rm0, 1));
            rm0 = fmaxf(rm0, __shfl_xor_sync(0xffffffffu, rm0, 2));
            rm1 = fmaxf(rm1, __shfl_xor_sync(0xffffffffu, rm1, 1));
            rm1 = fmaxf(rm1, __shfl_xor_sync(0xffffffffu, rm1, 2));

            float nm0 = fmaxf(m0, rm0), nm1 = fmaxf(m1, rm1);
            float a0 = exp2f_fast(m0 - nm0), a1 = exp2f_fast(m1 - nm1);
            m0 = nm0; m1 = nm1;
#pragma unroll
            for (int nt = 0; nt < 10; ++nt) {
                O[nt][0] *= a0; O[nt][1] *= a0;
                O[nt][2] *= a1; O[nt][3] *= a1;
            }
            float s0 = 0.f, s1 = 0.f;
#pragma unroll
            for (int nt = 0; nt < 8; ++nt) {
                S[nt][0] = exp2f_fast(S[nt][0] - nm0); s0 += S[nt][0];
                S[nt][1] = exp2f_fast(S[nt][1] - nm0); s0 += S[nt][1];
                S[nt][2] = exp2f_fast(S[nt][2] - nm1); s1 += S[nt][2];
                S[nt][3] = exp2f_fast(S[nt][3] - nm1); s1 += S[nt][3];
            }
            s0 += __shfl_xor_sync(0xffffffffu, s0, 1);
            s0 += __shfl_xor_sync(0xffffffffu, s0, 2);
            s1 += __shfl_xor_sync(0xffffffffu, s1, 1);
            s1 += __shfl_xor_sync(0xffffffffu, s1, 2);
            l0 = l0*a0 + s0;
            l1 = l1*a1 + s1;

            // ---- P -> A fragments (hi/lo, in-register) ----
            uint32_t PH[4][4], PL[4][4];
#pragma unroll
            for (int g = 0; g < 4; ++g) {
                uint32_t hb[8]; float lf[8];
                split2(S[2*g][0], hb[0], lf[0]);  split2(S[2*g][1], hb[1], lf[1]);
                split2(S[2*g][2], hb[2], lf[2]);  split2(S[2*g][3], hb[3], lf[3]);
                split2(S[2*g+1][0], hb[4], lf[4]); split2(S[2*g+1][1], hb[5], lf[5]);
                split2(S[2*g+1][2], hb[6], lf[6]); split2(S[2*g+1][3], hb[7], lf[7]);
                PH[g][0] = hb[0] | (hb[1] << 16);
                PH[g][1] = hb[2] | (hb[3] << 16);
                PH[g][2] = hb[4] | (hb[5] << 16);
                PH[g][3] = hb[6] | (hb[7] << 16);
                PL[g][0] = packbf(lf[0], lf[1]);
                PL[g][1] = packbf(lf[2], lf[3]);
                PL[g][2] = packbf(lf[4], lf[5]);
                PL[g][3] = packbf(lf[6], lf[7]);
            }

            // ---- O += PH*VH + PL*VH + PH*VL ----
            const int sel = lane >> 3;
#pragma unroll
            for (int g = 0; g < 4; ++g) {
                int krow = g*16 + (lane & 7) + (sel & 1)*8;
#pragma unroll
                for (int np = 0; np < 5; ++np) {
                    uint32_t bv[4], bw[4];
                    int noff = np*16 + (sel >> 1)*8;
                    ldm_x4_t(bv, s2u(&sm.kv.vh[krow*STR + noff]));
                    ldm_x4_t(bw, s2u(&sm.kv.vl[krow*STR + noff]));
                    mma16816(O[2*np],   PH[g], bv[0], bv[1]);
                    mma16816(O[2*np],   PL[g], bv[0], bv[1]);
                    mma16816(O[2*np],   PH[g], bw[0], bw[1]);
                    mma16816(O[2*np+1], PH[g], bv[2], bv[3]);
                    mma16816(O[2*np+1], PL[g], bv[2], bv[3]);
                    mma16816(O[2*np+1], PH[g], bw[2], bw[3]);
                }
            }
        }
        __syncthreads();
    }

    // ---- epilogue: normalize, write bf16 hi/lo ----
    const float i0 = 1.f / l0, i1 = 1.f / l1;
    const size_t base0 = (size_t)(b*SEQ + qrow) * HH + h * HDIM;
    const size_t base1 = base0 + (size_t)8 * HH;
#pragma unroll
    for (int nt = 0; nt < 10; ++nt) {
        int d = nt*8 + (lane & 3)*2;
        {
            float v0 = O[nt][0]*i0, v1 = O[nt][1]*i0;
            uint32_t h0,h1; float f0,f1;
            split2(v0,h0,f0); split2(v1,h1,f1);
            *(uint32_t*)&ahi[base0 + d] = h0 | (h1 << 16);
            *(uint32_t*)&alo[base0 + d] = packbf(f0, f1);
        }
        {
            float v0 = O[nt][2]*i1, v1 = O[nt][3]*i1;
            uint32_t h0,h1; float f0,f1;
            split2(v0,h0,f0); split2(v1,h1,f1);
            *(uint32_t*)&ahi[base1 + d] = h0 | (h1 << 16);
            *(uint32_t*)&alo[base1 + d] = packbf(f0, f1);
        }
    }
}

// ---------------------------------------------------------------------------
// Launch
// ---------------------------------------------------------------------------
extern "C" void kernel_launch(void* const* d_in, const int* in_sizes, int n_in,
                              void* d_out, int out_size)
{
    const float* hidden  = (const float*)d_in[0];
    // d_in[1] = attention_mask: exact additive causal mask; implemented directly.
    const float* scaling = (const float*)d_in[2];
    const float* qkv_w   = (const float*)d_in[3];
    const float* qkv_b   = (const float*)d_in[4];
    const float* o_w     = (const float*)d_in[5];
    const float* o_b     = (const float*)d_in[6];
    float* out = (float*)d_out;

    float *qkv; __nv_bfloat16 *hhi, *hlo, *w1h, *w1l, *w2h, *w2l, *ahi, *alo;
    cudaGetSymbolAddress((void**)&qkv, g_qkv);
    cudaGetSymbolAddress((void**)&hhi, g_h_hi);
    cudaGetSymbolAddress((void**)&hlo, g_h_lo);
    cudaGetSymbolAddress((void**)&w1h, g_w1_hi);
    cudaGetSymbolAddress((void**)&w1l, g_w1_lo);
    cudaGetSymbolAddress((void**)&w2h, g_w2_hi);
    cudaGetSymbolAddress((void**)&w2l, g_w2_lo);
    cudaGetSymbolAddress((void**)&ahi, g_a_hi);
    cudaGetSymbolAddress((void**)&alo, g_a_lo);

    cudaFuncSetAttribute(mma_gemm<0>, cudaFuncAttributeMaxDynamicSharedMemorySize, GSMEM);
    cudaFuncSetAttribute(mma_gemm<1>, cudaFuncAttributeMaxDynamicSharedMemorySize, GSMEM);

    scale_kernel<<<1, 128>>>(scaling);

    {   // hidden -> hi/lo
        int n4 = (MTOT * DMODEL) / 4;
        cvt_split<<<(n4 + 255) / 256, 256>>>(hidden, hhi, hlo, n4);
    }
    {   // qkv_w -> hi/lo
        int n4 = (NQKV * DMODEL) / 4;
        cvt_split<<<(n4 + 255) / 256, 256>>>(qkv_w, w1h, w1l, n4);
    }

    // QKV projection: [8192,1280] @ [3840,1280]^T -> g_qkv (bias + q-scale)
    mma_gemm<0><<<dim3(NQKV / 128, MTOT / 128), 256, GSMEM>>>(
        hhi, hlo, w1h, w1l, qkv_b, qkv, NQKV);

    // Tensor-core flash attention -> bf16 hi/lo
    flash_tc<<<dim3(SEQ / 128, BATCH * NHEAD), 256>>>(qkv, ahi, alo);

    {   // o_w -> hi/lo
        int n4 = (DMODEL * HH) / 4;
        cvt_split<<<(n4 + 255) / 256, 256>>>(o_w, w2h, w2l, n4);
    }

    // Output projection: [8192,1280] @ [1280,1280]^T -> out (bias)
    mma_gemm<1><<<dim3(DMODEL / 128, MTOT / 128), 256, GSMEM>>>(
        ahi, alo, w2h, w2l, o_b, out, DMODEL);
}